// round 10
// baseline (speedup 1.0000x reference)
#include <cuda_runtime.h>
#include <cuda_bf16.h>
#include <cstdint>

#define D        256
#define KCODES   8192
#define BM       256                 // rows per CTA (8 warps x 2 m16 tiles)
#define BN       128                 // codes per chunk
#define NCHUNK   (KCODES / BN)
#define THREADS  256
#define NROWS    32768
#define DEPTH    6                   // per-lane top-DEPTH
#define NCAND    (4 * DEPTH)         // 24 candidates per row

// ---- smem: double-buffered e4m3 B chunk + c2 ----
#define BROWB     272                              // bytes per B row (256 data + 16 pad)
#define BUF_BYTES (BN * BROWB)                     // 34816
#define C2_OFF    (2 * BUF_BYTES)                  // [2][128] f32
#define SMEM_TOTAL (C2_OFF + 2 * BN * 4 + 256)

__device__ __align__(16) float g_c2[KCODES];
__device__ __align__(16) uint8_t g_cbe[KCODES * D];   // e4m3 codebook (2MB)
__device__ int g_cand[NROWS * NCAND];

// ======================= helpers =======================
__device__ __forceinline__ uint32_t smem_u32(const void* p) {
    uint32_t a;
    asm("{ .reg .u64 t; cvta.to.shared.u64 t, %1; cvt.u32.u64 %0, t; }" : "=r"(a) : "l"(p));
    return a;
}
// pack 4 f32 -> 4 e4m3 bytes (x in lowest byte)
__device__ __forceinline__ uint32_t q4e(float4 v) {
    uint32_t r;
    asm("{ .reg .b16 l, h;\n\t"
        "cvt.rn.satfinite.e4m3x2.f32 l, %2, %1;\n\t"
        "cvt.rn.satfinite.e4m3x2.f32 h, %4, %3;\n\t"
        "mov.b32 %0, {l, h}; }"
        : "=r"(r) : "f"(v.x), "f"(v.y), "f"(v.z), "f"(v.w));
    return r;
}
// sorted depth-6 insert, caller guarantees s < tv[5]
__device__ __forceinline__ void ins6(float* tv, int* ti, float s, int gi) {
    bool b0 = s < tv[0], b1 = s < tv[1], b2 = s < tv[2],
         b3 = s < tv[3], b4 = s < tv[4];
    tv[5] = b4 ? tv[4] : s;             ti[5] = b4 ? ti[4] : gi;
    tv[4] = b3 ? tv[3] : (b4 ? s : tv[4]);  ti[4] = b3 ? ti[3] : (b4 ? gi : ti[4]);
    tv[3] = b2 ? tv[2] : (b3 ? s : tv[3]);  ti[3] = b2 ? ti[2] : (b3 ? gi : ti[3]);
    tv[2] = b1 ? tv[1] : (b2 ? s : tv[2]);  ti[2] = b1 ? ti[1] : (b2 ? gi : ti[2]);
    tv[1] = b0 ? tv[0] : (b1 ? s : tv[1]);  ti[1] = b0 ? ti[0] : (b1 ? gi : ti[1]);
    tv[0] = b0 ? s : tv[0];             ti[0] = b0 ? gi : ti[0];
}

#define CP_ASYNC16(dst, src) \
    asm volatile("cp.async.ca.shared.global [%0], [%1], 16;" :: "r"(dst), "l"(src))
#define CP_COMMIT() asm volatile("cp.async.commit_group;" ::: "memory")
#define CP_WAIT1()  asm volatile("cp.async.wait_group 1;" ::: "memory")

#define MMA_FP8(Cr, Ar, B0, B1) \
    asm volatile("mma.sync.aligned.m16n8k32.row.col.f32.e4m3.e4m3.f32 " \
        "{%0,%1,%2,%3}, {%4,%5,%6,%7}, {%8,%9}, {%0,%1,%2,%3};" \
        : "+f"((Cr)[0]), "+f"((Cr)[1]), "+f"((Cr)[2]), "+f"((Cr)[3]) \
        : "r"((Ar)[0]), "r"((Ar)[1]), "r"((Ar)[2]), "r"((Ar)[3]), \
          "r"(B0), "r"(B1))

#define LDSM_X4(r0, r1, r2, r3, addr) \
    asm volatile("ldmatrix.sync.aligned.m8n8.x4.shared.b16 {%0,%1,%2,%3}, [%4];" \
        : "=r"(r0), "=r"(r1), "=r"(r2), "=r"(r3) : "r"(addr))

// ---------------- kernel 0: codebook f32 -> e4m3 ----------------
__global__ void prep_kernel(const float* __restrict__ cb) {
    int t = blockIdx.x * blockDim.x + threadIdx.x;     // 0..262143
    const float4* s4 = (const float4*)cb;
    float4 v0 = s4[t * 2];
    float4 v1 = s4[t * 2 + 1];
    ((uint2*)g_cbe)[t] = make_uint2(q4e(v0), q4e(v1));
}

// ---------------- kernel 1: codebook squared norms (exact f32) ----------------
__global__ void c2_kernel(const float* __restrict__ cb) {
    int warp = (blockIdx.x * blockDim.x + threadIdx.x) >> 5;
    int lane = threadIdx.x & 31;
    if (warp >= KCODES) return;
    const float4* row = (const float4*)(cb + (size_t)warp * D);
    float4 a = row[lane];
    float4 b = row[lane + 32];
    float s = a.x*a.x + a.y*a.y + a.z*a.z + a.w*a.w
            + b.x*b.x + b.y*b.y + b.z*b.z + b.w*b.w;
    #pragma unroll
    for (int off = 16; off; off >>= 1) s += __shfl_down_sync(0xffffffffu, s, off);
    if (lane == 0) g_c2[warp] = s;
}

// ---------------- kernel 2: fp8 MMA candidate search ----------------
extern __shared__ char smem_raw[];

__device__ __forceinline__ void load_chunk_async(uint32_t sbase, int buf,
                                                 int n0, int tid) {
    uint32_t dstb = sbase + buf * BUF_BYTES;
    const uint8_t* cbe = g_cbe;
    #pragma unroll
    for (int i = 0; i < 8; i++) {
        int e = i * THREADS + tid;            // 0..2047 16B-units (128 rows x 16 units)
        int n = e >> 4, u = e & 15;
        uint32_t dst = dstb + n * BROWB + u * 16;
        const uint8_t* src = cbe + (size_t)(n0 + n) * D + u * 16;
        CP_ASYNC16(dst, src);
    }
    if (tid < 32) {
        uint32_t dst = sbase + C2_OFF + buf * 512 + tid * 16;
        CP_ASYNC16(dst, (const float*)g_c2 + n0 + tid * 4);
    }
}

__global__ __launch_bounds__(THREADS, 1)
void vq_main(const float* __restrict__ h)
{
    const uint32_t sbase = smem_u32(smem_raw);
    const float* c2s = (const float*)(smem_raw + C2_OFF);
    const int tid  = threadIdx.x;
    const int lane = tid & 31;
    const int rowbase = blockIdx.x * BM + (tid >> 5) * 32;

    // ---- prefetch chunk 0 ----
    load_chunk_async(sbase, 0, 0, tid);
    CP_COMMIT();

    // ---- A fragments: 2 mt x 8 k32 x 4 regs (4 x e4m3), converted once ----
    uint32_t a[2][8][4];
    #pragma unroll
    for (int mt = 0; mt < 2; mt++) {
        #pragma unroll
        for (int k = 0; k < 8; k++) {
            int r = rowbase + mt * 16 + (lane >> 2);
            int c = k * 32 + (lane & 3) * 4;
            const float* p0 = h + (size_t)r * D + c;
            const float* p1 = h + (size_t)(r + 8) * D + c;
            a[mt][k][0] = q4e(*(const float4*)p0);
            a[mt][k][1] = q4e(*(const float4*)p1);
            a[mt][k][2] = q4e(*(const float4*)(p0 + 16));
            a[mt][k][3] = q4e(*(const float4*)(p1 + 16));
        }
    }

    const uint32_t laneoff = (uint32_t)((((lane >> 4) & 1) * 8 + (lane & 7)) * BROWB
                                        + ((lane >> 3) & 1) * 16);

    // ---- per-lane top-6 (value,idx) for 4 row-slots ----
    float tv[4][DEPTH];
    int   ti[4][DEPTH];
    #pragma unroll
    for (int s = 0; s < 4; s++)
        #pragma unroll
        for (int d = 0; d < DEPTH; d++) { tv[s][d] = 3.4e38f; ti[s][d] = 0; }

    for (int ch = 0; ch < NCHUNK; ch++) {
        const int buf = ch & 1;
        const int n0  = ch * BN;

        __syncthreads();
        if (ch + 1 < NCHUNK) load_chunk_async(sbase, buf ^ 1, n0 + BN, tid);
        CP_COMMIT();
        CP_WAIT1();
        __syncthreads();

        const uint32_t bsm = sbase + buf * BUF_BYTES + laneoff;
        const float* c2p = c2s + buf * BN;

        #pragma unroll
        for (int pr = 0; pr < 8; pr++) {            // 16 cols per pr
            float C[4][4];
            #pragma unroll
            for (int q = 0; q < 4; q++)
                #pragma unroll
                for (int e = 0; e < 4; e++) C[q][e] = 0.0f;

            const uint32_t bpr = bsm + (uint32_t)(pr * 16) * BROWB;
            #pragma unroll
            for (int k = 0; k < 8; k++) {
                uint32_t b0, b1, b2, b3;
                LDSM_X4(b0, b1, b2, b3, bpr + k * 32);
                MMA_FP8(C[0], a[0][k], b0, b1);
                MMA_FP8(C[1], a[0][k], b2, b3);
                MMA_FP8(C[2], a[1][k], b0, b1);
                MMA_FP8(C[3], a[1][k], b2, b3);
            }

            // epilogue: score = c2 - 2*dot; guarded rare-path insert
            #pragma unroll
            for (int mt = 0; mt < 2; mt++) {
                #pragma unroll
                for (int nh = 0; nh < 2; nh++) {
                    const float* f = C[mt * 2 + nh];
                    int lc = pr * 16 + nh * 8 + (lane & 3) * 2;
                    int gi = n0 + lc;
                    float ca = c2p[lc], cb2 = c2p[lc + 1];
                    int sl0 = mt * 2, sl1 = mt * 2 + 1;
                    float s0 = fmaf(-2.0f, f[0], ca);
                    float s1 = fmaf(-2.0f, f[1], cb2);
                    float s2 = fmaf(-2.0f, f[2], ca);
                    float s3 = fmaf(-2.0f, f[3], cb2);
                    if (s0 < tv[sl0][DEPTH-1]) ins6(tv[sl0], ti[sl0], s0, gi);
                    if (s1 < tv[sl0][DEPTH-1]) ins6(tv[sl0], ti[sl0], s1, gi + 1);
                    if (s2 < tv[sl1][DEPTH-1]) ins6(tv[sl1], ti[sl1], s2, gi);
                    if (s3 < tv[sl1][DEPTH-1]) ins6(tv[sl1], ti[sl1], s3, gi + 1);
                }
            }
        }
    }

    // ---- publish NCAND candidates per row (4 lanes x depth 6) ----
    #pragma unroll
    for (int s = 0; s < 4; s++) {
        int row  = rowbase + (s >> 1) * 16 + (lane >> 2) + (s & 1) * 8;
        int base = row * NCAND + (lane & 3) * DEPTH;
        #pragma unroll
        for (int d = 0; d < DEPTH; d++)
            g_cand[base + d] = ti[s][d];
    }
}

// ---------------- kernel 3: exact fp32 rescore + gather ----------------
__global__ __launch_bounds__(256)
void rescore_kernel(const float* __restrict__ h, const float* __restrict__ cb,
                    float* __restrict__ outQ, float* __restrict__ outIdxF,
                    int* __restrict__ outIdxI)
{
    const int row  = blockIdx.x * 8 + (threadIdx.x >> 5);
    const int lane = threadIdx.x & 31;

    const float4* hr = (const float4*)(h + (size_t)row * D);
    float4 h0 = hr[lane], h1 = hr[lane + 32];

    float bd = 3.4e38f;
    int   bi = KCODES;
    #pragma unroll
    for (int j = 0; j < NCAND; j++) {
        int ci = g_cand[row * NCAND + j];
        const float4* cr = (const float4*)(cb + (size_t)ci * D);
        float4 c0 = cr[lane], c1 = cr[lane + 32];
        float dot = h0.x*c0.x + h0.y*c0.y + h0.z*c0.z + h0.w*c0.w
                  + h1.x*c1.x + h1.y*c1.y + h1.z*c1.z + h1.w*c1.w;
        #pragma unroll
        for (int o = 16; o; o >>= 1) dot += __shfl_xor_sync(0xffffffffu, dot, o);
        float dist = fmaf(-2.0f, dot, g_c2[ci]);
        if (dist < bd || (dist == bd && ci < bi)) { bd = dist; bi = ci; }
    }

    const float4* wr = (const float4*)(cb + (size_t)bi * D);
    if (outQ) {
        float4* o4 = (float4*)(outQ + (size_t)row * D);
        o4[lane]      = wr[lane];
        o4[lane + 32] = wr[lane + 32];
    }
    if (lane == 0) {
        if (outIdxF) outIdxF[row] = (float)bi;
        if (outIdxI) outIdxI[row] = bi;
    }
}

// ---------------- launch ----------------
extern "C" void kernel_launch(void* const* d_in, const int* in_sizes, int n_in,
                              void* d_out, int out_size)
{
    const float* h  = (const float*)d_in[0];
    const float* cb = (const float*)d_in[1];
    const int N = in_sizes[0] / D;   // 32768 rows

    prep_kernel<<<KCODES * D / 8 / 256, 256>>>(cb);
    c2_kernel<<<KCODES / 8, 256>>>(cb);

    cudaFuncSetAttribute(vq_main, cudaFuncAttributeMaxDynamicSharedMemorySize,
                         SMEM_TOTAL);
    vq_main<<<N / BM, THREADS, SMEM_TOTAL>>>(h);

    float* outQ    = nullptr;
    float* outIdxF = nullptr;
    int*   outIdxI = nullptr;
    long long nd = (long long)N * D;
    if (out_size >= nd) {
        outQ = (float*)d_out;
        if (out_size >= nd + N) outIdxF = (float*)d_out + nd;
    } else {
        outIdxI = (int*)d_out;
    }

    rescore_kernel<<<N / 8, 256>>>(h, cb, outQ, outIdxF, outIdxI);
}

// round 11
// speedup vs baseline: 2.3487x; 2.3487x over previous
#include <cuda_runtime.h>
#include <cuda_fp16.h>
#include <cstdint>

#define D        256
#define KCODES   8192
#define BM       256                 // rows per CTA (8 warps x 2 m16 tiles)
#define BN       64                  // codes per chunk
#define NCHUNK   (KCODES / BN)
#define THREADS  256
#define NROWS    32768
#define DEPTH    4                   // per-lane top-DEPTH
#define NCAND    (4 * DEPTH)         // 16 candidates per row

// ---- smem: double-buffered f16 B chunk + c2 ----
#define BROWB     528                              // bytes per B row (512 data + 16 pad)
#define BUF_BYTES (BN * BROWB)                     // 33792
#define C2_OFF    (2 * BUF_BYTES)                  // [2][64] f32
#define SMEM_TOTAL (C2_OFF + 2 * BN * 4 + 256)

__device__ __align__(16) float g_c2[KCODES];
__device__ __align__(16) __half g_cbh[KCODES * D];   // f16 codebook (4MB)
__device__ int g_cand[NROWS * NCAND];

// ======================= helpers =======================
__device__ __forceinline__ uint32_t smem_u32(const void* p) {
    uint32_t a;
    asm("{ .reg .u64 t; cvta.to.shared.u64 t, %1; cvt.u32.u64 %0, t; }" : "=r"(a) : "l"(p));
    return a;
}
__device__ __forceinline__ uint32_t packh(float lo, float hi) {
    uint32_t r;
    asm("cvt.rn.f16x2.f32 %0, %1, %2;" : "=r"(r) : "f"(hi), "f"(lo));
    return r;
}
// sorted depth-4 insert (tv[0] best); caller guarantees s < tv[3]
__device__ __forceinline__ void ins4f(float* tv, int* ti, float s, int gi) {
    bool b0 = s < tv[0], b1 = s < tv[1], b2 = s < tv[2];
    tv[3] = b2 ? tv[2] : s;                 ti[3] = b2 ? ti[2] : gi;
    tv[2] = b1 ? tv[1] : (b2 ? s : tv[2]);  ti[2] = b1 ? ti[1] : (b2 ? gi : ti[2]);
    tv[1] = b0 ? tv[0] : (b1 ? s : tv[1]);  ti[1] = b0 ? ti[0] : (b1 ? gi : ti[1]);
    tv[0] = b0 ? s : tv[0];                 ti[0] = b0 ? gi : ti[0];
}

#define CP_ASYNC16(dst, src) \
    asm volatile("cp.async.ca.shared.global [%0], [%1], 16;" :: "r"(dst), "l"(src))
#define CP_COMMIT() asm volatile("cp.async.commit_group;" ::: "memory")
#define CP_WAIT1()  asm volatile("cp.async.wait_group 1;" ::: "memory")

// fp16 MMA with fp16 accumulators: C/D = 2 x .f16x2 regs
#define MMA_F16(Cr, Ar, B0, B1) \
    asm volatile("mma.sync.aligned.m16n8k16.row.col.f16.f16.f16.f16 " \
        "{%0,%1}, {%2,%3,%4,%5}, {%6,%7}, {%0,%1};" \
        : "+r"((Cr)[0]), "+r"((Cr)[1]) \
        : "r"((Ar)[0]), "r"((Ar)[1]), "r"((Ar)[2]), "r"((Ar)[3]), \
          "r"(B0), "r"(B1))

#define LDSM_X4(r0, r1, r2, r3, addr) \
    asm volatile("ldmatrix.sync.aligned.m8n8.x4.shared.b16 {%0,%1,%2,%3}, [%4];" \
        : "=r"(r0), "=r"(r1), "=r"(r2), "=r"(r3) : "r"(addr))

// ---------------- kernel 0: codebook f32 -> f16 ----------------
__global__ void prep_kernel(const float* __restrict__ cb) {
    int t = blockIdx.x * blockDim.x + threadIdx.x;   // 0..262143 (8 elems each)
    const float4* s4 = (const float4*)cb;
    float4 v0 = s4[t * 2];
    float4 v1 = s4[t * 2 + 1];
    uint4 o;
    o.x = packh(v0.x, v0.y);
    o.y = packh(v0.z, v0.w);
    o.z = packh(v1.x, v1.y);
    o.w = packh(v1.z, v1.w);
    ((uint4*)g_cbh)[t] = o;
}

// ---------------- kernel 1: codebook squared norms (exact f32) ----------------
__global__ void c2_kernel(const float* __restrict__ cb) {
    int warp = (blockIdx.x * blockDim.x + threadIdx.x) >> 5;
    int lane = threadIdx.x & 31;
    if (warp >= KCODES) return;
    const float4* row = (const float4*)(cb + (size_t)warp * D);
    float4 a = row[lane];
    float4 b = row[lane + 32];
    float s = a.x*a.x + a.y*a.y + a.z*a.z + a.w*a.w
            + b.x*b.x + b.y*b.y + b.z*b.z + b.w*b.w;
    #pragma unroll
    for (int off = 16; off; off >>= 1) s += __shfl_down_sync(0xffffffffu, s, off);
    if (lane == 0) g_c2[warp] = s;
}

// ---------------- kernel 2: f16 HMMA candidate search ----------------
extern __shared__ char smem_raw[];

__device__ __forceinline__ void load_chunk_async(uint32_t sbase, int buf,
                                                 int n0, int tid) {
    uint32_t dstb = sbase + buf * BUF_BYTES;
    const __half* cbh = g_cbh;
    #pragma unroll
    for (int i = 0; i < 8; i++) {
        int e = i * THREADS + tid;            // 0..2047 16B-units (64 rows x 32 units)
        int n = e >> 5, u = e & 31;           // 32 units (=256 f16) per row
        uint32_t dst = dstb + n * BROWB + u * 16;
        const __half* src = cbh + (size_t)(n0 + n) * D + u * 8;
        CP_ASYNC16(dst, src);
    }
    if (tid < 16) {
        uint32_t dst = sbase + C2_OFF + buf * 256 + tid * 16;
        CP_ASYNC16(dst, (const float*)g_c2 + n0 + tid * 4);
    }
}

__global__ __launch_bounds__(THREADS, 1)
void vq_main(const float* __restrict__ h)
{
    const uint32_t sbase = smem_u32(smem_raw);
    const float* c2s = (const float*)(smem_raw + C2_OFF);
    const int tid  = threadIdx.x;
    const int lane = tid & 31;
    const int rowbase = blockIdx.x * BM + (tid >> 5) * 32;

    // ---- prefetch chunk 0 ----
    load_chunk_async(sbase, 0, 0, tid);
    CP_COMMIT();

    // ---- A fragments: 2 m16-tiles x 16 ksteps x 4 regs (f16x2), loaded once ----
    uint32_t a[2][16][4];
    #pragma unroll
    for (int mt = 0; mt < 2; mt++) {
        #pragma unroll
        for (int k = 0; k < 16; k++) {
            int r = rowbase + mt * 16 + (lane >> 2);
            int c = k * 16 + (lane & 3) * 2;
            const float* p0 = h + (size_t)r * D + c;
            const float* p1 = h + (size_t)(r + 8) * D + c;
            float2 v00 = *(const float2*)p0;
            float2 v01 = *(const float2*)(p0 + 8);
            float2 v10 = *(const float2*)p1;
            float2 v11 = *(const float2*)(p1 + 8);
            a[mt][k][0] = packh(v00.x, v00.y);
            a[mt][k][1] = packh(v10.x, v10.y);
            a[mt][k][2] = packh(v01.x, v01.y);
            a[mt][k][3] = packh(v11.x, v11.y);
        }
    }

    // ldmatrix lane offset: matrices (n0-7,k0-7), (n0-7,k8-15), (n8-15,k0-7), (n8-15,k8-15)
    const uint32_t laneoff = (uint32_t)((((lane >> 4) & 1) * 8 + (lane & 7)) * BROWB
                                        + ((lane >> 3) & 1) * 16);

    // ---- per-lane top-4 (value,idx) for 4 row-slots ----
    float tv[4][DEPTH];
    int   ti[4][DEPTH];
    #pragma unroll
    for (int s = 0; s < 4; s++)
        #pragma unroll
        for (int d = 0; d < DEPTH; d++) { tv[s][d] = 3.4e38f; ti[s][d] = 0; }

    for (int ch = 0; ch < NCHUNK; ch++) {
        const int buf = ch & 1;
        const int n0  = ch * BN;

        __syncthreads();
        if (ch + 1 < NCHUNK) load_chunk_async(sbase, buf ^ 1, n0 + BN, tid);
        CP_COMMIT();
        CP_WAIT1();
        __syncthreads();

        const uint32_t bsm = sbase + buf * BUF_BYTES + laneoff;
        const float* c2p = c2s + buf * BN;

        #pragma unroll
        for (int pr = 0; pr < 4; pr++) {            // 16 cols per pr
            uint32_t C[4][2];
            #pragma unroll
            for (int q = 0; q < 4; q++) { C[q][0] = 0u; C[q][1] = 0u; }

            const uint32_t bpr = bsm + (uint32_t)(pr * 16) * BROWB;
            #pragma unroll
            for (int k = 0; k < 16; k++) {
                uint32_t b0, b1, b2, b3;
                LDSM_X4(b0, b1, b2, b3, bpr + k * 32);
                MMA_F16(C[0], a[0][k], b0, b1);
                MMA_F16(C[1], a[0][k], b2, b3);
                MMA_F16(C[2], a[1][k], b0, b1);
                MMA_F16(C[3], a[1][k], b2, b3);
            }

            // epilogue: score = c2 - 2*dot (dot in f16 pairs); guarded insert
            #pragma unroll
            for (int mt = 0; mt < 2; mt++) {
                #pragma unroll
                for (int nh = 0; nh < 2; nh++) {
                    const uint32_t* Cr = C[mt * 2 + nh];
                    int lc = pr * 16 + nh * 8 + (lane & 3) * 2;
                    int gi = n0 + lc;
                    float ca = c2p[lc], cb2 = c2p[lc + 1];
                    float2 f0 = __half22float2(*(const __half2*)&Cr[0]);  // rows r
                    float2 f1 = __half22float2(*(const __half2*)&Cr[1]);  // rows r+8
                    int sl0 = mt * 2, sl1 = mt * 2 + 1;
                    float s0 = fmaf(-2.0f, f0.x, ca);
                    float s1 = fmaf(-2.0f, f0.y, cb2);
                    float s2 = fmaf(-2.0f, f1.x, ca);
                    float s3 = fmaf(-2.0f, f1.y, cb2);
                    if (s0 < tv[sl0][DEPTH-1]) ins4f(tv[sl0], ti[sl0], s0, gi);
                    if (s1 < tv[sl0][DEPTH-1]) ins4f(tv[sl0], ti[sl0], s1, gi + 1);
                    if (s2 < tv[sl1][DEPTH-1]) ins4f(tv[sl1], ti[sl1], s2, gi);
                    if (s3 < tv[sl1][DEPTH-1]) ins4f(tv[sl1], ti[sl1], s3, gi + 1);
                }
            }
        }
    }

    // ---- publish 16 candidates per row (4 lanes x depth 4) ----
    #pragma unroll
    for (int s = 0; s < 4; s++) {
        int row  = rowbase + (s >> 1) * 16 + (lane >> 2) + (s & 1) * 8;
        int base = row * NCAND + (lane & 3) * DEPTH;
        #pragma unroll
        for (int d = 0; d < DEPTH; d++)
            g_cand[base + d] = ti[s][d];
    }
}

// ---------------- kernel 3: exact fp32 rescore + gather ----------------
__global__ __launch_bounds__(256)
void rescore_kernel(const float* __restrict__ h, const float* __restrict__ cb,
                    float* __restrict__ outQ, float* __restrict__ outIdxF,
                    int* __restrict__ outIdxI)
{
    const int row  = blockIdx.x * 8 + (threadIdx.x >> 5);
    const int lane = threadIdx.x & 31;

    const float4* hr = (const float4*)(h + (size_t)row * D);
    float4 h0 = hr[lane], h1 = hr[lane + 32];

    float bd = 3.4e38f;
    int   bi = KCODES;
    #pragma unroll
    for (int j = 0; j < NCAND; j++) {
        int ci = g_cand[row * NCAND + j];
        const float4* cr = (const float4*)(cb + (size_t)ci * D);
        float4 c0 = cr[lane], c1 = cr[lane + 32];
        float dot = h0.x*c0.x + h0.y*c0.y + h0.z*c0.z + h0.w*c0.w
                  + h1.x*c1.x + h1.y*c1.y + h1.z*c1.z + h1.w*c1.w;
        #pragma unroll
        for (int o = 16; o; o >>= 1) dot += __shfl_xor_sync(0xffffffffu, dot, o);
        float dist = fmaf(-2.0f, dot, g_c2[ci]);
        if (dist < bd || (dist == bd && ci < bi)) { bd = dist; bi = ci; }
    }

    const float4* wr = (const float4*)(cb + (size_t)bi * D);
    if (outQ) {
        float4* o4 = (float4*)(outQ + (size_t)row * D);
        o4[lane]      = wr[lane];
        o4[lane + 32] = wr[lane + 32];
    }
    if (lane == 0) {
        if (outIdxF) outIdxF[row] = (float)bi;
        if (outIdxI) outIdxI[row] = bi;
    }
}

// ---------------- launch ----------------
extern "C" void kernel_launch(void* const* d_in, const int* in_sizes, int n_in,
                              void* d_out, int out_size)
{
    const float* h  = (const float*)d_in[0];
    const float* cb = (const float*)d_in[1];
    const int N = in_sizes[0] / D;   // 32768 rows

    prep_kernel<<<KCODES * D / 8 / 256, 256>>>(cb);
    c2_kernel<<<KCODES / 8, 256>>>(cb);

    cudaFuncSetAttribute(vq_main, cudaFuncAttributeMaxDynamicSharedMemorySize,
                         SMEM_TOTAL);
    vq_main<<<N / BM, THREADS, SMEM_TOTAL>>>(h);

    float* outQ    = nullptr;
    float* outIdxF = nullptr;
    int*   outIdxI = nullptr;
    long long nd = (long long)N * D;
    if (out_size >= nd) {
        outQ = (float*)d_out;
        if (out_size >= nd + N) outIdxF = (float*)d_out + nd;
    } else {
        outIdxI = (int*)d_out;
    }

    rescore_kernel<<<N / 8, 256>>>(h, cb, outQ, outIdxF, outIdxI);
}

// round 12
// speedup vs baseline: 2.3715x; 1.0097x over previous
#include <cuda_runtime.h>
#include <cuda_bf16.h>
#include <cstdint>

#define D        256
#define KCODES   8192
#define BM       256                 // rows per CTA (8 warps x 2 m16 tiles)
#define BN       128                 // codes per chunk
#define NCHUNK   (KCODES / BN)
#define THREADS  256
#define NROWS    32768
#define DEPTH    4                   // per-lane top-DEPTH
#define NCAND    (4 * DEPTH)         // 16 candidates per row

// ---- smem: double-buffered bf16 B chunk + c2 ----
#define BROWB     528                              // bytes per B row (512 data + 16 pad)
#define BUF_BYTES (BN * BROWB)                     // 67584
#define C2_OFF    (2 * BUF_BYTES)                  // [2][128] f32
#define SMEM_TOTAL (C2_OFF + 2 * BN * 4 + 256)

__device__ __align__(16) float g_c2[KCODES];
__device__ __align__(16) __nv_bfloat16 g_cbh[KCODES * D];   // bf16 codebook (4MB)
__device__ int g_cand[NROWS * NCAND];

// ======================= helpers =======================
__device__ __forceinline__ uint32_t smem_u32(const void* p) {
    uint32_t a;
    asm("{ .reg .u64 t; cvta.to.shared.u64 t, %1; cvt.u32.u64 %0, t; }" : "=r"(a) : "l"(p));
    return a;
}
__device__ __forceinline__ uint32_t packbf(float lo, float hi) {
    uint32_t r;
    asm("cvt.rn.bf16x2.f32 %0, %1, %2;" : "=r"(r) : "f"(hi), "f"(lo));
    return r;
}
// sorted depth-4 insert (tv[0] best); caller guarantees s < tv[3]
__device__ __forceinline__ void ins4f(float* tv, int* ti, float s, int gi) {
    bool b0 = s < tv[0], b1 = s < tv[1], b2 = s < tv[2];
    tv[3] = b2 ? tv[2] : s;                 ti[3] = b2 ? ti[2] : gi;
    tv[2] = b1 ? tv[1] : (b2 ? s : tv[2]);  ti[2] = b1 ? ti[1] : (b2 ? gi : ti[2]);
    tv[1] = b0 ? tv[0] : (b1 ? s : tv[1]);  ti[1] = b0 ? ti[0] : (b1 ? gi : ti[1]);
    tv[0] = b0 ? s : tv[0];                 ti[0] = b0 ? gi : ti[0];
}

#define CP_ASYNC16(dst, src) \
    asm volatile("cp.async.ca.shared.global [%0], [%1], 16;" :: "r"(dst), "l"(src))
#define CP_COMMIT() asm volatile("cp.async.commit_group;" ::: "memory")
#define CP_WAIT1()  asm volatile("cp.async.wait_group 1;" ::: "memory")

#define MMA_BF16(Cr, Ar, B0, B1) \
    asm volatile("mma.sync.aligned.m16n8k16.row.col.f32.bf16.bf16.f32 " \
        "{%0,%1,%2,%3}, {%4,%5,%6,%7}, {%8,%9}, {%0,%1,%2,%3};" \
        : "+f"((Cr)[0]), "+f"((Cr)[1]), "+f"((Cr)[2]), "+f"((Cr)[3]) \
        : "r"((Ar)[0]), "r"((Ar)[1]), "r"((Ar)[2]), "r"((Ar)[3]), \
          "r"(B0), "r"(B1))

#define LDSM_X4(r0, r1, r2, r3, addr) \
    asm volatile("ldmatrix.sync.aligned.m8n8.x4.shared.b16 {%0,%1,%2,%3}, [%4];" \
        : "=r"(r0), "=r"(r1), "=r"(r2), "=r"(r3) : "r"(addr))

// ---------------- kernel 0: codebook f32 -> bf16 AND exact norms, fused ----------------
// one warp per codebook row
__global__ void prep_kernel(const float* __restrict__ cb) {
    int row  = (blockIdx.x * blockDim.x + threadIdx.x) >> 5;
    int lane = threadIdx.x & 31;
    if (row >= KCODES) return;
    const float4* r4 = (const float4*)(cb + (size_t)row * D);
    float4 a = r4[lane];
    float4 b = r4[lane + 32];
    // bf16 pack (each lane covers 8 elems: 4 from first half, 4 from second)
    uint2* dst = (uint2*)(g_cbh + (size_t)row * D);
    dst[lane]      = make_uint2(packbf(a.x, a.y), packbf(a.z, a.w));
    dst[lane + 32] = make_uint2(packbf(b.x, b.y), packbf(b.z, b.w));
    // exact f32 norm
    float s = a.x*a.x + a.y*a.y + a.z*a.z + a.w*a.w
            + b.x*b.x + b.y*b.y + b.z*b.z + b.w*b.w;
    #pragma unroll
    for (int off = 16; off; off >>= 1) s += __shfl_down_sync(0xffffffffu, s, off);
    if (lane == 0) g_c2[row] = s;
}

// ---------------- kernel 1: bf16 HMMA candidate search ----------------
extern __shared__ char smem_raw[];

__device__ __forceinline__ void load_chunk_async(uint32_t sbase, int buf,
                                                 int n0, int tid) {
    uint32_t dstb = sbase + buf * BUF_BYTES;
    const __nv_bfloat16* cbh = g_cbh;
    #pragma unroll
    for (int i = 0; i < 16; i++) {
        int e = i * THREADS + tid;            // 0..4095 16B-units (128 rows x 32 units)
        int n = e >> 5, u = e & 31;           // 32 units (=256 bf16) per row
        uint32_t dst = dstb + n * BROWB + u * 16;
        const __nv_bfloat16* src = cbh + (size_t)(n0 + n) * D + u * 8;
        CP_ASYNC16(dst, src);
    }
    if (tid < 32) {
        uint32_t dst = sbase + C2_OFF + buf * 512 + tid * 16;
        CP_ASYNC16(dst, (const float*)g_c2 + n0 + tid * 4);
    }
}

__global__ __launch_bounds__(THREADS, 1)
void vq_main(const float* __restrict__ h)
{
    const uint32_t sbase = smem_u32(smem_raw);
    const float* c2s = (const float*)(smem_raw + C2_OFF);
    const int tid  = threadIdx.x;
    const int lane = tid & 31;
    const int rowbase = blockIdx.x * BM + (tid >> 5) * 32;

    // ---- prefetch chunk 0 ----
    load_chunk_async(sbase, 0, 0, tid);
    CP_COMMIT();

    // ---- A fragments: 2 m16-tiles x 16 ksteps x 4 regs (bf16x2), loaded once ----
    uint32_t a[2][16][4];
    #pragma unroll
    for (int mt = 0; mt < 2; mt++) {
        #pragma unroll
        for (int k = 0; k < 16; k++) {
            int r = rowbase + mt * 16 + (lane >> 2);
            int c = k * 16 + (lane & 3) * 2;
            const float* p0 = h + (size_t)r * D + c;
            const float* p1 = h + (size_t)(r + 8) * D + c;
            float2 v00 = *(const float2*)p0;
            float2 v01 = *(const float2*)(p0 + 8);
            float2 v10 = *(const float2*)p1;
            float2 v11 = *(const float2*)(p1 + 8);
            a[mt][k][0] = packbf(v00.x, v00.y);
            a[mt][k][1] = packbf(v10.x, v10.y);
            a[mt][k][2] = packbf(v01.x, v01.y);
            a[mt][k][3] = packbf(v11.x, v11.y);
        }
    }

    // ldmatrix lane offset
    const uint32_t laneoff = (uint32_t)((((lane >> 4) & 1) * 8 + (lane & 7)) * BROWB
                                        + ((lane >> 3) & 1) * 16);

    // ---- per-lane top-4 (value,idx) for 4 row-slots ----
    float tv[4][DEPTH];
    int   ti[4][DEPTH];
    #pragma unroll
    for (int s = 0; s < 4; s++)
        #pragma unroll
        for (int d = 0; d < DEPTH; d++) { tv[s][d] = 3.4e38f; ti[s][d] = 0; }

    for (int ch = 0; ch < NCHUNK; ch++) {
        const int buf = ch & 1;
        const int n0  = ch * BN;

        __syncthreads();
        if (ch + 1 < NCHUNK) load_chunk_async(sbase, buf ^ 1, n0 + BN, tid);
        CP_COMMIT();
        CP_WAIT1();
        __syncthreads();

        const uint32_t bsm = sbase + buf * BUF_BYTES + laneoff;
        const float* c2p = c2s + buf * BN;

        #pragma unroll
        for (int pr = 0; pr < 8; pr++) {            // 16 cols per pr
            float C[4][4];
            #pragma unroll
            for (int q = 0; q < 4; q++)
                #pragma unroll
                for (int e = 0; e < 4; e++) C[q][e] = 0.0f;

            const uint32_t bpr = bsm + (uint32_t)(pr * 16) * BROWB;
            #pragma unroll
            for (int k = 0; k < 16; k++) {
                uint32_t b0, b1, b2, b3;
                LDSM_X4(b0, b1, b2, b3, bpr + k * 32);
                MMA_BF16(C[0], a[0][k], b0, b1);
                MMA_BF16(C[1], a[0][k], b2, b3);
                MMA_BF16(C[2], a[1][k], b0, b1);
                MMA_BF16(C[3], a[1][k], b2, b3);
            }

            // epilogue: score = c2 - 2*dot; guarded rare-path insert
            #pragma unroll
            for (int mt = 0; mt < 2; mt++) {
                #pragma unroll
                for (int nh = 0; nh < 2; nh++) {
                    const float* f = C[mt * 2 + nh];
                    int lc = pr * 16 + nh * 8 + (lane & 3) * 2;
                    int gi = n0 + lc;
                    float ca = c2p[lc], cb2 = c2p[lc + 1];
                    int sl0 = mt * 2, sl1 = mt * 2 + 1;
                    float s0 = fmaf(-2.0f, f[0], ca);
                    float s1 = fmaf(-2.0f, f[1], cb2);
                    float s2 = fmaf(-2.0f, f[2], ca);
                    float s3 = fmaf(-2.0f, f[3], cb2);
                    if (s0 < tv[sl0][DEPTH-1]) ins4f(tv[sl0], ti[sl0], s0, gi);
                    if (s1 < tv[sl0][DEPTH-1]) ins4f(tv[sl0], ti[sl0], s1, gi + 1);
                    if (s2 < tv[sl1][DEPTH-1]) ins4f(tv[sl1], ti[sl1], s2, gi);
                    if (s3 < tv[sl1][DEPTH-1]) ins4f(tv[sl1], ti[sl1], s3, gi + 1);
                }
            }
        }
    }

    // ---- publish 16 candidates per row (4 lanes x depth 4) ----
    #pragma unroll
    for (int s = 0; s < 4; s++) {
        int row  = rowbase + (s >> 1) * 16 + (lane >> 2) + (s & 1) * 8;
        int base = row * NCAND + (lane & 3) * DEPTH;
        #pragma unroll
        for (int d = 0; d < DEPTH; d++)
            g_cand[base + d] = ti[s][d];
    }
}

// ---------------- kernel 2: exact fp32 rescore + gather ----------------
__global__ __launch_bounds__(256)
void rescore_kernel(const float* __restrict__ h, const float* __restrict__ cb,
                    float* __restrict__ outQ, float* __restrict__ outIdxF,
                    int* __restrict__ outIdxI)
{
    const int row  = blockIdx.x * 8 + (threadIdx.x >> 5);
    const int lane = threadIdx.x & 31;

    const float4* hr = (const float4*)(h + (size_t)row * D);
    float4 h0 = hr[lane], h1 = hr[lane + 32];

    float bd = 3.4e38f;
    int   bi = KCODES;
    #pragma unroll
    for (int j = 0; j < NCAND; j++) {
        int ci = g_cand[row * NCAND + j];
        const float4* cr = (const float4*)(cb + (size_t)ci * D);
        float4 c0 = cr[lane], c1 = cr[lane + 32];
        float dot = h0.x*c0.x + h0.y*c0.y + h0.z*c0.z + h0.w*c0.w
                  + h1.x*c1.x + h1.y*c1.y + h1.z*c1.z + h1.w*c1.w;
        #pragma unroll
        for (int o = 16; o; o >>= 1) dot += __shfl_xor_sync(0xffffffffu, dot, o);
        float dist = fmaf(-2.0f, dot, g_c2[ci]);
        if (dist < bd || (dist == bd && ci < bi)) { bd = dist; bi = ci; }
    }

    const float4* wr = (const float4*)(cb + (size_t)bi * D);
    if (outQ) {
        float4* o4 = (float4*)(outQ + (size_t)row * D);
        o4[lane]      = wr[lane];
        o4[lane + 32] = wr[lane + 32];
    }
    if (lane == 0) {
        if (outIdxF) outIdxF[row] = (float)bi;
        if (outIdxI) outIdxI[row] = bi;
    }
}

// ---------------- launch ----------------
extern "C" void kernel_launch(void* const* d_in, const int* in_sizes, int n_in,
                              void* d_out, int out_size)
{
    const float* h  = (const float*)d_in[0];
    const float* cb = (const float*)d_in[1];
    const int N = in_sizes[0] / D;   // 32768 rows

    prep_kernel<<<KCODES / 8, 256>>>(cb);

    cudaFuncSetAttribute(vq_main, cudaFuncAttributeMaxDynamicSharedMemorySize,
                         SMEM_TOTAL);
    vq_main<<<N / BM, THREADS, SMEM_TOTAL>>>(h);

    float* outQ    = nullptr;
    float* outIdxF = nullptr;
    int*   outIdxI = nullptr;
    long long nd = (long long)N * D;
    if (out_size >= nd) {
        outQ = (float*)d_out;
        if (out_size >= nd + N) outIdxF = (float*)d_out + nd;
    } else {
        outIdxI = (int*)d_out;
    }

    rescore_kernel<<<N / 8, 256>>>(h, cb, outQ, outIdxF, outIdxI);
}

// round 13
// speedup vs baseline: 3.1533x; 1.3297x over previous
#include <cuda_runtime.h>
#include <cuda_bf16.h>
#include <cstdint>

#define D        256
#define KCODES   8192
#define BM       256                 // rows per CTA (8 warps x 2 m16 tiles)
#define BN       128                 // codes per chunk
#define NCHUNK   (KCODES / BN)
#define THREADS  256
#define NROWS    32768
#define NCAND    8                   // 4 lanes x top-2

// ---- smem: double-buffered bf16 B chunk + c2 ----
#define BROWB     528                              // bytes per B row (512 data + 16 pad)
#define BUF_BYTES (BN * BROWB)                     // 67584
#define C2_OFF    (2 * BUF_BYTES)                  // [2][128] f32
#define SMEM_TOTAL (C2_OFF + 2 * BN * 4 + 256)

__device__ __align__(16) float g_c2[KCODES];
__device__ __align__(16) __nv_bfloat16 g_cbh[KCODES * D];   // bf16 codebook (4MB)
__device__ int g_cand[NROWS * NCAND];

// ======================= helpers =======================
__device__ __forceinline__ uint32_t smem_u32(const void* p) {
    uint32_t a;
    asm("{ .reg .u64 t; cvta.to.shared.u64 t, %1; cvt.u32.u64 %0, t; }" : "=r"(a) : "l"(p));
    return a;
}
__device__ __forceinline__ uint32_t packbf(float lo, float hi) {
    uint32_t r;
    asm("cvt.rn.bf16x2.f32 %0, %1, %2;" : "=r"(r) : "f"(hi), "f"(lo));
    return r;
}

#define CP_ASYNC16(dst, src) \
    asm volatile("cp.async.ca.shared.global [%0], [%1], 16;" :: "r"(dst), "l"(src))
#define CP_COMMIT() asm volatile("cp.async.commit_group;" ::: "memory")
#define CP_WAIT1()  asm volatile("cp.async.wait_group 1;" ::: "memory")

#define MMA_BF16(Cr, Ar, B0, B1) \
    asm volatile("mma.sync.aligned.m16n8k16.row.col.f32.bf16.bf16.f32 " \
        "{%0,%1,%2,%3}, {%4,%5,%6,%7}, {%8,%9}, {%0,%1,%2,%3};" \
        : "+f"((Cr)[0]), "+f"((Cr)[1]), "+f"((Cr)[2]), "+f"((Cr)[3]) \
        : "r"((Ar)[0]), "r"((Ar)[1]), "r"((Ar)[2]), "r"((Ar)[3]), \
          "r"(B0), "r"(B1))

#define LDSM_X4(r0, r1, r2, r3, addr) \
    asm volatile("ldmatrix.sync.aligned.m8n8.x4.shared.b16 {%0,%1,%2,%3}, [%4];" \
        : "=r"(r0), "=r"(r1), "=r"(r2), "=r"(r3) : "r"(addr))

// ---------------- kernel 0: codebook f32 -> bf16 AND exact norms, fused ----------------
__global__ void prep_kernel(const float* __restrict__ cb) {
    int row  = (blockIdx.x * blockDim.x + threadIdx.x) >> 5;
    int lane = threadIdx.x & 31;
    if (row >= KCODES) return;
    const float4* r4 = (const float4*)(cb + (size_t)row * D);
    float4 a = r4[lane];
    float4 b = r4[lane + 32];
    uint2* dst = (uint2*)(g_cbh + (size_t)row * D);
    dst[lane]      = make_uint2(packbf(a.x, a.y), packbf(a.z, a.w));
    dst[lane + 32] = make_uint2(packbf(b.x, b.y), packbf(b.z, b.w));
    float s = a.x*a.x + a.y*a.y + a.z*a.z + a.w*a.w
            + b.x*b.x + b.y*b.y + b.z*b.z + b.w*b.w;
    #pragma unroll
    for (int off = 16; off; off >>= 1) s += __shfl_down_sync(0xffffffffu, s, off);
    if (lane == 0) g_c2[row] = s;
}

// ---------------- kernel 1: bf16 HMMA candidate search ----------------
extern __shared__ char smem_raw[];

__device__ __forceinline__ void load_chunk_async(uint32_t sbase, int buf,
                                                 int n0, int tid) {
    uint32_t dstb = sbase + buf * BUF_BYTES;
    const __nv_bfloat16* cbh = g_cbh;
    #pragma unroll
    for (int i = 0; i < 16; i++) {
        int e = i * THREADS + tid;            // 0..4095 16B-units (128 rows x 32 units)
        int n = e >> 5, u = e & 31;           // 32 units (=256 bf16) per row
        uint32_t dst = dstb + n * BROWB + u * 16;
        const __nv_bfloat16* src = cbh + (size_t)(n0 + n) * D + u * 8;
        CP_ASYNC16(dst, src);
    }
    if (tid < 32) {
        uint32_t dst = sbase + C2_OFF + buf * 512 + tid * 16;
        CP_ASYNC16(dst, (const float*)g_c2 + n0 + tid * 4);
    }
}

__global__ __launch_bounds__(THREADS, 1)
void vq_main(const float* __restrict__ h)
{
    const uint32_t sbase = smem_u32(smem_raw);
    const float* c2s = (const float*)(smem_raw + C2_OFF);
    const int tid  = threadIdx.x;
    const int lane = tid & 31;
    const int rowbase = blockIdx.x * BM + (tid >> 5) * 32;

    // ---- prefetch chunk 0 ----
    load_chunk_async(sbase, 0, 0, tid);
    CP_COMMIT();

    // ---- A fragments: 2 m16-tiles x 16 ksteps x 4 regs (bf16x2), loaded once ----
    uint32_t a[2][16][4];
    #pragma unroll
    for (int mt = 0; mt < 2; mt++) {
        #pragma unroll
        for (int k = 0; k < 16; k++) {
            int r = rowbase + mt * 16 + (lane >> 2);
            int c = k * 16 + (lane & 3) * 2;
            const float* p0 = h + (size_t)r * D + c;
            const float* p1 = h + (size_t)(r + 8) * D + c;
            float2 v00 = *(const float2*)p0;
            float2 v01 = *(const float2*)(p0 + 8);
            float2 v10 = *(const float2*)p1;
            float2 v11 = *(const float2*)(p1 + 8);
            a[mt][k][0] = packbf(v00.x, v00.y);
            a[mt][k][1] = packbf(v10.x, v10.y);
            a[mt][k][2] = packbf(v01.x, v01.y);
            a[mt][k][3] = packbf(v11.x, v11.y);
        }
    }

    // ldmatrix lane offset
    const uint32_t laneoff = (uint32_t)((((lane >> 4) & 1) * 8 + (lane & 7)) * BROWB
                                        + ((lane >> 3) & 1) * 16);

    // ---- per-lane top-2 for 4 row-slots (R6 epilogue, predicable arms) ----
    float t1v[4], t2v[4];
    int   t1i[4], t2i[4];
    #pragma unroll
    for (int s = 0; s < 4; s++) { t1v[s] = 3.4e38f; t2v[s] = 3.4e38f; t1i[s] = 0; t2i[s] = 0; }

    for (int ch = 0; ch < NCHUNK; ch++) {
        const int buf = ch & 1;
        const int n0  = ch * BN;

        __syncthreads();
        if (ch + 1 < NCHUNK) load_chunk_async(sbase, buf ^ 1, n0 + BN, tid);
        CP_COMMIT();
        CP_WAIT1();
        __syncthreads();

        const uint32_t bsm = sbase + buf * BUF_BYTES + laneoff;
        const float* c2p = c2s + buf * BN;

        #pragma unroll
        for (int pr = 0; pr < 8; pr++) {            // 16 cols per pr
            float C[4][4];
            #pragma unroll
            for (int q = 0; q < 4; q++)
                #pragma unroll
                for (int e = 0; e < 4; e++) C[q][e] = 0.0f;

            const uint32_t bpr = bsm + (uint32_t)(pr * 16) * BROWB;
            #pragma unroll
            for (int k = 0; k < 16; k++) {
                uint32_t b0, b1, b2, b3;
                LDSM_X4(b0, b1, b2, b3, bpr + k * 32);
                MMA_BF16(C[0], a[0][k], b0, b1);
                MMA_BF16(C[1], a[0][k], b2, b3);
                MMA_BF16(C[2], a[1][k], b0, b1);
                MMA_BF16(C[3], a[1][k], b2, b3);
            }

            // epilogue: score = c2 - 2*dot, top-2 insert (small predicable arms)
            #pragma unroll
            for (int mt = 0; mt < 2; mt++) {
                #pragma unroll
                for (int nh = 0; nh < 2; nh++) {
                    const float* f = C[mt * 2 + nh];
                    int lc = pr * 16 + nh * 8 + (lane & 3) * 2;
                    int gi = n0 + lc;
                    float ca = c2p[lc], cb2 = c2p[lc + 1];
                    float s0a = fmaf(-2.0f, f[0], ca);
                    float s0b = fmaf(-2.0f, f[1], cb2);
                    float s1a = fmaf(-2.0f, f[2], ca);
                    float s1b = fmaf(-2.0f, f[3], cb2);
                    int sl0 = mt * 2, sl1 = mt * 2 + 1;
                    if (s0a < t1v[sl0]) { t2v[sl0]=t1v[sl0]; t2i[sl0]=t1i[sl0]; t1v[sl0]=s0a; t1i[sl0]=gi; }
                    else if (s0a < t2v[sl0]) { t2v[sl0]=s0a; t2i[sl0]=gi; }
                    if (s0b < t1v[sl0]) { t2v[sl0]=t1v[sl0]; t2i[sl0]=t1i[sl0]; t1v[sl0]=s0b; t1i[sl0]=gi+1; }
                    else if (s0b < t2v[sl0]) { t2v[sl0]=s0b; t2i[sl0]=gi+1; }
                    if (s1a < t1v[sl1]) { t2v[sl1]=t1v[sl1]; t2i[sl1]=t1i[sl1]; t1v[sl1]=s1a; t1i[sl1]=gi; }
                    else if (s1a < t2v[sl1]) { t2v[sl1]=s1a; t2i[sl1]=gi; }
                    if (s1b < t1v[sl1]) { t2v[sl1]=t1v[sl1]; t2i[sl1]=t1i[sl1]; t1v[sl1]=s1b; t1i[sl1]=gi+1; }
                    else if (s1b < t2v[sl1]) { t2v[sl1]=s1b; t2i[sl1]=gi+1; }
                }
            }
        }
    }

    // ---- publish 8 candidates per row (4 lanes x top-2) ----
    #pragma unroll
    for (int s = 0; s < 4; s++) {
        int row  = rowbase + (s >> 1) * 16 + (lane >> 2) + (s & 1) * 8;
        int base = row * NCAND + (lane & 3) * 2;
        g_cand[base]     = t1i[s];
        g_cand[base + 1] = t2i[s];
    }
}

// ---------------- kernel 2: exact fp32 rescore + gather ----------------
__global__ __launch_bounds__(256)
void rescore_kernel(const float* __restrict__ h, const float* __restrict__ cb,
                    float* __restrict__ outQ, float* __restrict__ outIdxF,
                    int* __restrict__ outIdxI)
{
    const int row  = blockIdx.x * 8 + (threadIdx.x >> 5);
    const int lane = threadIdx.x & 31;

    const float4* hr = (const float4*)(h + (size_t)row * D);
    float4 h0 = hr[lane], h1 = hr[lane + 32];

    float bd = 3.4e38f;
    int   bi = KCODES;
    #pragma unroll
    for (int j = 0; j < NCAND; j++) {
        int ci = g_cand[row * NCAND + j];
        const float4* cr = (const float4*)(cb + (size_t)ci * D);
        float4 c0 = cr[lane], c1 = cr[lane + 32];
        float dot = h0.x*c0.x + h0.y*c0.y + h0.z*c0.z + h0.w*c0.w
                  + h1.x*c1.x + h1.y*c1.y + h1.z*c1.z + h1.w*c1.w;
        #pragma unroll
        for (int o = 16; o; o >>= 1) dot += __shfl_xor_sync(0xffffffffu, dot, o);
        float dist = fmaf(-2.0f, dot, g_c2[ci]);
        if (dist < bd || (dist == bd && ci < bi)) { bd = dist; bi = ci; }
    }

    const float4* wr = (const float4*)(cb + (size_t)bi * D);
    if (outQ) {
        float4* o4 = (float4*)(outQ + (size_t)row * D);
        o4[lane]      = wr[lane];
        o4[lane + 32] = wr[lane + 32];
    }
    if (lane == 0) {
        if (outIdxF) outIdxF[row] = (float)bi;
        if (outIdxI) outIdxI[row] = bi;
    }
}

// ---------------- launch ----------------
extern "C" void kernel_launch(void* const* d_in, const int* in_sizes, int n_in,
                              void* d_out, int out_size)
{
    const float* h  = (const float*)d_in[0];
    const float* cb = (const float*)d_in[1];
    const int N = in_sizes[0] / D;   // 32768 rows

    prep_kernel<<<KCODES / 8, 256>>>(cb);

    cudaFuncSetAttribute(vq_main, cudaFuncAttributeMaxDynamicSharedMemorySize,
                         SMEM_TOTAL);
    vq_main<<<N / BM, THREADS, SMEM_TOTAL>>>(h);

    float* outQ    = nullptr;
    float* outIdxF = nullptr;
    int*   outIdxI = nullptr;
    long long nd = (long long)N * D;
    if (out_size >= nd) {
        outQ = (float*)d_out;
        if (out_size >= nd + N) outIdxF = (float*)d_out + nd;
    } else {
        outIdxI = (int*)d_out;
    }

    rescore_kernel<<<N / 8, 256>>>(h, cb, outQ, outIdxF, outIdxI);
}

// round 14
// speedup vs baseline: 3.2899x; 1.0433x over previous
#include <cuda_runtime.h>
#include <cuda_bf16.h>
#include <cstdint>

#define D        256
#define KCODES   8192
#define BM       128                 // rows per CTA (4 warps x 2 m16 tiles)
#define BN       64                  // codes per chunk
#define KQ       2048                // codes per CTA (quarter codebook)
#define NQ       4                   // quarters
#define NCHUNK   (KQ / BN)           // 32
#define THREADS  128
#define NROWS    32768
#define NCAND    32                  // 4 quarters x 4 lanes x top-2

// ---- smem: double-buffered bf16 B chunk + c2 ----
#define BROWB     528                              // bytes per B row (512 data + 16 pad)
#define BUF_BYTES (BN * BROWB)                     // 33792
#define C2_OFF    (2 * BUF_BYTES)                  // [2][64] f32
#define SMEM_TOTAL (C2_OFF + 2 * BN * 4 + 256)    // 68352

__device__ __align__(16) float g_c2[KCODES];
__device__ __align__(16) __nv_bfloat16 g_cbh[KCODES * D];   // bf16 codebook (4MB)
__device__ float g_cs[NROWS * NCAND];              // candidate bf16 scores
__device__ int   g_ci[NROWS * NCAND];              // candidate indices

// ======================= helpers =======================
__device__ __forceinline__ uint32_t smem_u32(const void* p) {
    uint32_t a;
    asm("{ .reg .u64 t; cvta.to.shared.u64 t, %1; cvt.u32.u64 %0, t; }" : "=r"(a) : "l"(p));
    return a;
}
__device__ __forceinline__ uint32_t packbf(float lo, float hi) {
    uint32_t r;
    asm("cvt.rn.bf16x2.f32 %0, %1, %2;" : "=r"(r) : "f"(hi), "f"(lo));
    return r;
}

#define CP_ASYNC16(dst, src) \
    asm volatile("cp.async.ca.shared.global [%0], [%1], 16;" :: "r"(dst), "l"(src))
#define CP_COMMIT() asm volatile("cp.async.commit_group;" ::: "memory")
#define CP_WAIT1()  asm volatile("cp.async.wait_group 1;" ::: "memory")

#define MMA_BF16(Cr, Ar, B0, B1) \
    asm volatile("mma.sync.aligned.m16n8k16.row.col.f32.bf16.bf16.f32 " \
        "{%0,%1,%2,%3}, {%4,%5,%6,%7}, {%8,%9}, {%0,%1,%2,%3};" \
        : "+f"((Cr)[0]), "+f"((Cr)[1]), "+f"((Cr)[2]), "+f"((Cr)[3]) \
        : "r"((Ar)[0]), "r"((Ar)[1]), "r"((Ar)[2]), "r"((Ar)[3]), \
          "r"(B0), "r"(B1))

#define LDSM_X4(r0, r1, r2, r3, addr) \
    asm volatile("ldmatrix.sync.aligned.m8n8.x4.shared.b16 {%0,%1,%2,%3}, [%4];" \
        : "=r"(r0), "=r"(r1), "=r"(r2), "=r"(r3) : "r"(addr))

// ---------------- kernel 0: codebook f32 -> bf16 AND exact norms, fused ----------------
__global__ void prep_kernel(const float* __restrict__ cb) {
    int row  = (blockIdx.x * blockDim.x + threadIdx.x) >> 5;
    int lane = threadIdx.x & 31;
    if (row >= KCODES) return;
    const float4* r4 = (const float4*)(cb + (size_t)row * D);
    float4 a = r4[lane];
    float4 b = r4[lane + 32];
    uint2* dst = (uint2*)(g_cbh + (size_t)row * D);
    dst[lane]      = make_uint2(packbf(a.x, a.y), packbf(a.z, a.w));
    dst[lane + 32] = make_uint2(packbf(b.x, b.y), packbf(b.z, b.w));
    float s = a.x*a.x + a.y*a.y + a.z*a.z + a.w*a.w
            + b.x*b.x + b.y*b.y + b.z*b.z + b.w*b.w;
    #pragma unroll
    for (int off = 16; off; off >>= 1) s += __shfl_down_sync(0xffffffffu, s, off);
    if (lane == 0) g_c2[row] = s;
}

// ---------------- kernel 1: bf16 HMMA candidate search (quarter-K CTAs) ----------------
extern __shared__ char smem_raw[];

__device__ __forceinline__ void load_chunk_async(uint32_t sbase, int buf,
                                                 int n0, int tid) {
    uint32_t dstb = sbase + buf * BUF_BYTES;
    const __nv_bfloat16* cbh = g_cbh;
    #pragma unroll
    for (int i = 0; i < 16; i++) {
        int e = i * THREADS + tid;            // 0..2047 16B-units (64 rows x 32 units)
        int n = e >> 5, u = e & 31;           // 32 units (=256 bf16) per row
        uint32_t dst = dstb + n * BROWB + u * 16;
        const __nv_bfloat16* src = cbh + (size_t)(n0 + n) * D + u * 8;
        CP_ASYNC16(dst, src);
    }
    if (tid < 16) {
        uint32_t dst = sbase + C2_OFF + buf * 256 + tid * 16;
        CP_ASYNC16(dst, (const float*)g_c2 + n0 + tid * 4);
    }
}

__global__ __launch_bounds__(THREADS, 2)
void vq_main(const float* __restrict__ h)
{
    const uint32_t sbase = smem_u32(smem_raw);
    const float* c2s = (const float*)(smem_raw + C2_OFF);
    const int tid  = threadIdx.x;
    const int lane = tid & 31;
    const int qid      = blockIdx.x >> 8;            // 0..3 (codebook quarter)
    const int rowtile  = blockIdx.x & 255;           // 0..255
    const int qbase    = qid * KQ;
    const int rowbase  = rowtile * BM + (tid >> 5) * 32;

    // ---- prefetch chunk 0 ----
    load_chunk_async(sbase, 0, qbase, tid);
    CP_COMMIT();

    // ---- A fragments: 2 m16-tiles x 16 ksteps x 4 regs (bf16x2), loaded once ----
    uint32_t a[2][16][4];
    #pragma unroll
    for (int mt = 0; mt < 2; mt++) {
        #pragma unroll
        for (int k = 0; k < 16; k++) {
            int r = rowbase + mt * 16 + (lane >> 2);
            int c = k * 16 + (lane & 3) * 2;
            const float* p0 = h + (size_t)r * D + c;
            const float* p1 = h + (size_t)(r + 8) * D + c;
            float2 v00 = *(const float2*)p0;
            float2 v01 = *(const float2*)(p0 + 8);
            float2 v10 = *(const float2*)p1;
            float2 v11 = *(const float2*)(p1 + 8);
            a[mt][k][0] = packbf(v00.x, v00.y);
            a[mt][k][1] = packbf(v10.x, v10.y);
            a[mt][k][2] = packbf(v01.x, v01.y);
            a[mt][k][3] = packbf(v11.x, v11.y);
        }
    }

    // ldmatrix lane offset
    const uint32_t laneoff = (uint32_t)((((lane >> 4) & 1) * 8 + (lane & 7)) * BROWB
                                        + ((lane >> 3) & 1) * 16);

    // ---- per-lane top-2 for 4 row-slots ----
    float t1v[4], t2v[4];
    int   t1i[4], t2i[4];
    #pragma unroll
    for (int s = 0; s < 4; s++) { t1v[s] = 3.4e38f; t2v[s] = 3.4e38f; t1i[s] = 0; t2i[s] = 0; }

    for (int ch = 0; ch < NCHUNK; ch++) {
        const int buf = ch & 1;
        const int n0  = qbase + ch * BN;

        __syncthreads();
        if (ch + 1 < NCHUNK) load_chunk_async(sbase, buf ^ 1, n0 + BN, tid);
        CP_COMMIT();
        CP_WAIT1();
        __syncthreads();

        const uint32_t bsm = sbase + buf * BUF_BYTES + laneoff;
        const float* c2p = c2s + buf * BN;

        #pragma unroll
        for (int pr = 0; pr < 4; pr++) {            // 16 cols per pr
            float C[4][4];
            #pragma unroll
            for (int q = 0; q < 4; q++)
                #pragma unroll
                for (int e = 0; e < 4; e++) C[q][e] = 0.0f;

            const uint32_t bpr = bsm + (uint32_t)(pr * 16) * BROWB;
            #pragma unroll
            for (int k = 0; k < 16; k++) {
                uint32_t b0, b1, b2, b3;
                LDSM_X4(b0, b1, b2, b3, bpr + k * 32);
                MMA_BF16(C[0], a[0][k], b0, b1);
                MMA_BF16(C[1], a[0][k], b2, b3);
                MMA_BF16(C[2], a[1][k], b0, b1);
                MMA_BF16(C[3], a[1][k], b2, b3);
            }

            // epilogue: score = c2 - 2*dot, top-2 insert (predicable arms)
            #pragma unroll
            for (int mt = 0; mt < 2; mt++) {
                #pragma unroll
                for (int nh = 0; nh < 2; nh++) {
                    const float* f = C[mt * 2 + nh];
                    int lc = pr * 16 + nh * 8 + (lane & 3) * 2;
                    int gi = n0 + lc;
                    float ca = c2p[lc], cb2 = c2p[lc + 1];
                    float s0a = fmaf(-2.0f, f[0], ca);
                    float s0b = fmaf(-2.0f, f[1], cb2);
                    float s1a = fmaf(-2.0f, f[2], ca);
                    float s1b = fmaf(-2.0f, f[3], cb2);
                    int sl0 = mt * 2, sl1 = mt * 2 + 1;
                    if (s0a < t1v[sl0]) { t2v[sl0]=t1v[sl0]; t2i[sl0]=t1i[sl0]; t1v[sl0]=s0a; t1i[sl0]=gi; }
                    else if (s0a < t2v[sl0]) { t2v[sl0]=s0a; t2i[sl0]=gi; }
                    if (s0b < t1v[sl0]) { t2v[sl0]=t1v[sl0]; t2i[sl0]=t1i[sl0]; t1v[sl0]=s0b; t1i[sl0]=gi+1; }
                    else if (s0b < t2v[sl0]) { t2v[sl0]=s0b; t2i[sl0]=gi+1; }
                    if (s1a < t1v[sl1]) { t2v[sl1]=t1v[sl1]; t2i[sl1]=t1i[sl1]; t1v[sl1]=s1a; t1i[sl1]=gi; }
                    else if (s1a < t2v[sl1]) { t2v[sl1]=s1a; t2i[sl1]=gi; }
                    if (s1b < t1v[sl1]) { t2v[sl1]=t1v[sl1]; t2i[sl1]=t1i[sl1]; t1v[sl1]=s1b; t1i[sl1]=gi+1; }
                    else if (s1b < t2v[sl1]) { t2v[sl1]=s1b; t2i[sl1]=gi+1; }
                }
            }
        }
    }

    // ---- publish 8 candidates per row for this quarter ----
    #pragma unroll
    for (int s = 0; s < 4; s++) {
        int row  = rowbase + (s >> 1) * 16 + (lane >> 2) + (s & 1) * 8;
        int base = row * NCAND + qid * 8 + (lane & 3) * 2;
        g_cs[base]     = t1v[s];  g_ci[base]     = t1i[s];
        g_cs[base + 1] = t2v[s];  g_ci[base + 1] = t2i[s];
    }
}

// ---------------- kernel 2: select 8-of-32 + exact fp32 rescore + gather ----------------
__global__ __launch_bounds__(256)
void rescore_kernel(const float* __restrict__ h, const float* __restrict__ cb,
                    float* __restrict__ outQ, float* __restrict__ outIdxF,
                    int* __restrict__ outIdxI)
{
    const int row  = blockIdx.x * 8 + (threadIdx.x >> 5);
    const int lane = threadIdx.x & 31;

    const float4* hr = (const float4*)(h + (size_t)row * D);
    float4 h0 = hr[lane], h1 = hr[lane + 32];

    // each lane holds one (score, idx) candidate
    float cs = g_cs[row * NCAND + lane];
    int   cidx = g_ci[row * NCAND + lane];

    float bd = 3.4e38f;
    int   bi = KCODES;
    #pragma unroll
    for (int it = 0; it < 8; it++) {
        // warp-argmin over remaining candidate scores (deterministic owner pick)
        float m = cs;
        #pragma unroll
        for (int o = 16; o; o >>= 1) m = fminf(m, __shfl_xor_sync(0xffffffffu, m, o));
        unsigned mask = __ballot_sync(0xffffffffu, cs == m);
        int owner = __ffs(mask) - 1;
        int ci = __shfl_sync(0xffffffffu, cidx, owner);
        if (lane == owner) cs = 3.4e38f;   // remove from pool

        // exact fp32 distance for candidate ci
        const float4* cr = (const float4*)(cb + (size_t)ci * D);
        float4 c0 = cr[lane], c1 = cr[lane + 32];
        float dot = h0.x*c0.x + h0.y*c0.y + h0.z*c0.z + h0.w*c0.w
                  + h1.x*c1.x + h1.y*c1.y + h1.z*c1.z + h1.w*c1.w;
        #pragma unroll
        for (int o = 16; o; o >>= 1) dot += __shfl_xor_sync(0xffffffffu, dot, o);
        float dist = fmaf(-2.0f, dot, g_c2[ci]);
        if (dist < bd || (dist == bd && ci < bi)) { bd = dist; bi = ci; }
    }

    const float4* wr = (const float4*)(cb + (size_t)bi * D);
    if (outQ) {
        float4* o4 = (float4*)(outQ + (size_t)row * D);
        o4[lane]      = wr[lane];
        o4[lane + 32] = wr[lane + 32];
    }
    if (lane == 0) {
        if (outIdxF) outIdxF[row] = (float)bi;
        if (outIdxI) outIdxI[row] = bi;
    }
}

// ---------------- launch ----------------
extern "C" void kernel_launch(void* const* d_in, const int* in_sizes, int n_in,
                              void* d_out, int out_size)
{
    const float* h  = (const float*)d_in[0];
    const float* cb = (const float*)d_in[1];
    const int N = in_sizes[0] / D;   // 32768 rows

    prep_kernel<<<KCODES / 8, 256>>>(cb);

    cudaFuncSetAttribute(vq_main, cudaFuncAttributeMaxDynamicSharedMemorySize,
                         SMEM_TOTAL);
    vq_main<<<(N / BM) * NQ, THREADS, SMEM_TOTAL>>>(h);

    float* outQ    = nullptr;
    float* outIdxF = nullptr;
    int*   outIdxI = nullptr;
    long long nd = (long long)N * D;
    if (out_size >= nd) {
        outQ = (float*)d_out;
        if (out_size >= nd + N) outIdxF = (float*)d_out + nd;
    } else {
        outIdxI = (int*)d_out;
    }

    rescore_kernel<<<N / 8, 256>>>(h, cb, outQ, outIdxF, outIdxI);
}